// round 15
// baseline (speedup 1.0000x reference)
#include <cuda_runtime.h>
#include <cuda_fp16.h>
#include <cstdint>

#define HASH_SIZE 10240
#define PROJ_DIM  128
#define MODEL_DIM 512
#define NBATCH    8
#define SEQ       8192
#define NTOK      (NBATCH * SEQ)

// CSR buckets: tokens grouped by hash value.
__device__ int g_hist[HASH_SIZE + 1];   // exclusive offsets after scan
__device__ int g_cursor[HASH_SIZE];     // scatter cursors
__device__ int g_hash[NTOK];            // per-token hash
__device__ int g_tok[NTOK];             // token ids grouped by hash

__device__ __forceinline__ uint32_t smem_u32(const void* p) {
    uint32_t a;
    asm("{ .reg .u64 t; cvta.to.shared.u64 t, %1; cvt.u32.u64 %0, t; }" : "=r"(a) : "l"(p));
    return a;
}
__device__ __forceinline__ void ldsm_x4(uint32_t& r0, uint32_t& r1,
                                        uint32_t& r2, uint32_t& r3, uint32_t addr) {
    asm volatile("ldmatrix.sync.aligned.m8n8.x4.shared.b16 {%0,%1,%2,%3}, [%4];"
                 : "=r"(r0), "=r"(r1), "=r"(r2), "=r"(r3) : "r"(addr));
}
__device__ __forceinline__ void mma_f16(float* d, const uint32_t* a, const uint32_t* b) {
    asm volatile("mma.sync.aligned.m16n8k16.row.col.f32.f16.f16.f32 "
                 "{%0,%1,%2,%3}, {%4,%5,%6,%7}, {%8,%9}, {%0,%1,%2,%3};"
                 : "+f"(d[0]), "+f"(d[1]), "+f"(d[2]), "+f"(d[3])
                 : "r"(a[0]), "r"(a[1]), "r"(a[2]), "r"(a[3]), "r"(b[0]), "r"(b[1]));
}
__device__ __forceinline__ uint32_t sw(int row, int chunk) {
    return (uint32_t)(row * 256 + ((chunk ^ (row & 7)) << 4));
}
__device__ __forceinline__ uint4 cvt8_f16(float4 a, float4 b) {
    __half2 h0 = __floats2half2_rn(a.x, a.y);
    __half2 h1 = __floats2half2_rn(a.z, a.w);
    __half2 h2 = __floats2half2_rn(b.x, b.y);
    __half2 h3 = __floats2half2_rn(b.z, b.w);
    return make_uint4(*(uint32_t*)&h0, *(uint32_t*)&h1,
                      *(uint32_t*)&h2, *(uint32_t*)&h3);
}
__device__ __forceinline__ int hash_at(const int* __restrict__ tok, int t) {
    const int s = t & (SEQ - 1);
    if (s == 0) return HASH_SIZE - 1;
    const int t1 = __ldg(tok + t);
    const int t0 = __ldg(tok + t - 1);
    // products < 2^31: no wrap; matches jnp.mod exactly
    return ((36313 * t1) ^ (27191 * t0)) % (HASH_SIZE - 1);
}

// ===========================================================================
// CSR bucket build: zero -> histogram -> scan -> scatter
// ===========================================================================
__global__ __launch_bounds__(256) void zero_kernel() {
    const int i = blockIdx.x * 256 + threadIdx.x;
    if (i <= HASH_SIZE) g_hist[i] = 0;
}

__global__ __launch_bounds__(256) void hash_hist_kernel(const int* __restrict__ tok) {
    const int t = blockIdx.x * 256 + threadIdx.x;
    if (t >= NTOK) return;
    const int h = hash_at(tok, t);
    g_hash[t] = h;
    atomicAdd(&g_hist[h], 1);
}

__global__ __launch_bounds__(1024) void scan_kernel() {
    __shared__ int s[1024];
    const int i = threadIdx.x;
    int loc[10];
    int sum = 0;
    #pragma unroll
    for (int k = 0; k < 10; k++) { loc[k] = g_hist[i * 10 + k]; sum += loc[k]; }
    s[i] = sum;
    __syncthreads();
    for (int off = 1; off < 1024; off <<= 1) {
        int v = (i >= off) ? s[i - off] : 0;
        __syncthreads();
        s[i] += v;
        __syncthreads();
    }
    int run = s[i] - sum;   // exclusive prefix
    #pragma unroll
    for (int k = 0; k < 10; k++) {
        g_hist[i * 10 + k]   = run;
        g_cursor[i * 10 + k] = run;
        run += loc[k];
    }
    if (i == 1023) g_hist[HASH_SIZE] = run;   // = NTOK
}

__global__ __launch_bounds__(256) void scatter_kernel() {
    const int t = blockIdx.x * 256 + threadIdx.x;
    if (t >= NTOK) return;
    const int h = g_hash[t];
    const int pos = atomicAdd(&g_cursor[h], 1);
    g_tok[pos] = t;
}

// ===========================================================================
// Fused GEMM + scatter: per tile (M=128 hash rows x N=64 cols), compute
// scale * E_tile @ P_tile^T on fp16 mma.sync, stage in smem, then write each
// row directly to all tokens hashing to it. The 21 MB table never exists.
// 296 persistent CTAs (2/SM), m-major tiles, A-slab reuse.
// ===========================================================================
#define A_OFF 0
#define B_OFF 32768
#define D_OFF 49152
#define D_STRIDE 68                     // floats; 68%32=4 -> conflict-lite
#define SMEM_DYN (49152 + 128 * D_STRIDE * 4 + 1024)
#define NTILES 640
#define NCTA   296

__global__ __launch_bounds__(256) void gemm_scatter_kernel(
    const float* __restrict__ E,
    const float* __restrict__ P,
    const float* __restrict__ scale_p,
    float* __restrict__ out)
{
    extern __shared__ char smem_raw[];
    const uint32_t sb0   = smem_u32(smem_raw);
    const uint32_t pad   = ((sb0 + 1023) & ~1023u) - sb0;
    char* smp            = smem_raw + pad;
    const uint32_t sbase = sb0 + pad;
    float* Dsm           = (float*)(smp + D_OFF);

    const int tid  = threadIdx.x;
    const int bid  = blockIdx.x;
    const int t0   = (bid * NTILES) / NCTA;
    const int t1   = ((bid + 1) * NTILES) / NCTA;
    const float s  = __ldg(scale_p);

    const int w    = tid >> 5;
    const int lane = tid & 31;
    const int wm   = w & 3;
    const int wn   = w >> 2;

    int rowA[2], rowB[2];
    #pragma unroll
    for (int mf = 0; mf < 2; mf++)
        rowA[mf] = wm * 32 + mf * 16 + (lane & 7) + (lane & 8);
    #pragma unroll
    for (int bp = 0; bp < 2; bp++)
        rowB[bp] = wn * 32 + bp * 16 + (lane & 7) + ((lane & 16) >> 1);
    const int ckA = lane >> 4;
    const int ckB = (lane >> 3) & 1;

    int cur_m = -1;
    for (int t = t0; t < t1; t++) {
        const int mi = t >> 3, ni = t & 7;
        const int m0 = mi * 128, n0 = ni * 64;

        // ---- copy+convert (A only on slab change)
        if (mi != cur_m) {
            #pragma unroll
            for (int i = 0; i < 8; i++) {
                const int idx = i * 256 + tid;
                const int row = idx >> 4, chunk = idx & 15;
                const float4* g = (const float4*)(E + (size_t)(m0 + row) * PROJ_DIM + chunk * 8);
                *(uint4*)(smp + A_OFF + sw(row, chunk)) = cvt8_f16(__ldg(g), __ldg(g + 1));
            }
            cur_m = mi;
        }
        #pragma unroll
        for (int i = 0; i < 4; i++) {
            const int idx = i * 256 + tid;
            const int row = idx >> 4, chunk = idx & 15;
            const float4* g = (const float4*)(P + (size_t)(n0 + row) * PROJ_DIM + chunk * 8);
            *(uint4*)(smp + B_OFF + sw(row, chunk)) = cvt8_f16(__ldg(g), __ldg(g + 1));
        }
        __syncthreads();

        // ---- MMA mainloop
        float acc[2][4][4];
        #pragma unroll
        for (int mf = 0; mf < 2; mf++)
            #pragma unroll
            for (int nf = 0; nf < 4; nf++)
                #pragma unroll
                for (int q = 0; q < 4; q++) acc[mf][nf][q] = 0.0f;

        #pragma unroll
        for (int kk = 0; kk < 8; kk++) {
            uint32_t ah[2][4];
            #pragma unroll
            for (int mf = 0; mf < 2; mf++) {
                const uint32_t off = sw(rowA[mf], 2 * kk + ckA);
                ldsm_x4(ah[mf][0], ah[mf][1], ah[mf][2], ah[mf][3], sbase + A_OFF + off);
            }
            uint32_t bh[4][2];
            #pragma unroll
            for (int bp = 0; bp < 2; bp++) {
                const uint32_t off = sw(rowB[bp], 2 * kk + ckB);
                ldsm_x4(bh[2 * bp][0], bh[2 * bp][1], bh[2 * bp + 1][0], bh[2 * bp + 1][1],
                        sbase + B_OFF + off);
            }
            #pragma unroll
            for (int mf = 0; mf < 2; mf++)
                #pragma unroll
                for (int nf = 0; nf < 4; nf++)
                    mma_f16(acc[mf][nf], ah[mf], bh[nf]);
        }

        // ---- stage D tile (scaled) into smem
        #pragma unroll
        for (int mf = 0; mf < 2; mf++) {
            const int rloc = wm * 32 + mf * 16 + (lane >> 2);
            #pragma unroll
            for (int nf = 0; nf < 4; nf++) {
                const int cloc = wn * 32 + nf * 8 + (lane & 3) * 2;
                Dsm[rloc * D_STRIDE + cloc]           = acc[mf][nf][0] * s;
                Dsm[rloc * D_STRIDE + cloc + 1]       = acc[mf][nf][1] * s;
                Dsm[(rloc + 8) * D_STRIDE + cloc]     = acc[mf][nf][2] * s;
                Dsm[(rloc + 8) * D_STRIDE + cloc + 1] = acc[mf][nf][3] * s;
            }
        }
        __syncthreads();

        // ---- scatter: warp w handles rows w*16 .. w*16+15
        const int half   = lane >> 4;          // half-warp id
        const int l16    = lane & 15;
        for (int rr = 0; rr < 16; rr++) {
            const int rloc = w * 16 + rr;
            const int m    = m0 + rloc;
            const int beg  = __ldg(&g_hist[m]);
            const int end  = __ldg(&g_hist[m + 1]);
            float4 v = *(float4*)&Dsm[rloc * D_STRIDE + l16 * 4];
            for (int j = beg + half; j < end; j += 2) {
                const int tk = __ldg(&g_tok[j]);
                __stcs((float4*)(out + (size_t)tk * MODEL_DIM + n0) + l16, v);
            }
        }
        __syncthreads();   // protect smem before next tile
    }
}

// ===========================================================================
// Inputs (metadata order): token_ids(i32), embed_weight(f32), proj_weight(f32), scale(f32[1])
// ===========================================================================
extern "C" void kernel_launch(void* const* d_in, const int* in_sizes, int n_in,
                              void* d_out, int out_size)
{
    const int*   tok   = (const int*)d_in[0];
    const float* E     = (const float*)d_in[1];
    const float* P     = (const float*)d_in[2];
    const float* scale = (const float*)d_in[3];
    float*       out   = (float*)d_out;

    cudaFuncSetAttribute(gemm_scatter_kernel,
                         cudaFuncAttributeMaxDynamicSharedMemorySize, SMEM_DYN);

    zero_kernel<<<(HASH_SIZE + 256) / 256, 256>>>();
    hash_hist_kernel<<<NTOK / 256, 256>>>(tok);
    scan_kernel<<<1, 1024>>>();
    scatter_kernel<<<NTOK / 256, 256>>>();
    gemm_scatter_kernel<<<NCTA, 256, SMEM_DYN>>>(E, P, scale, out);
}

// round 16
// speedup vs baseline: 1.6117x; 1.6117x over previous
#include <cuda_runtime.h>
#include <cuda_fp16.h>
#include <cstdint>

#define HASH_SIZE 10240
#define PROJ_DIM  128
#define MODEL_DIM 512
#define NBATCH    8
#define SEQ       8192

// Fused table: fused[h][m] = scale * sum_k embed[h][k] * proj[m][k]  (21 MB)
__device__ float g_fused[HASH_SIZE * MODEL_DIM];

__device__ __forceinline__ uint32_t smem_u32(const void* p) {
    uint32_t a;
    asm("{ .reg .u64 t; cvta.to.shared.u64 t, %1; cvt.u32.u64 %0, t; }" : "=r"(a) : "l"(p));
    return a;
}
__device__ __forceinline__ void ldsm_x4(uint32_t& r0, uint32_t& r1,
                                        uint32_t& r2, uint32_t& r3, uint32_t addr) {
    asm volatile("ldmatrix.sync.aligned.m8n8.x4.shared.b16 {%0,%1,%2,%3}, [%4];"
                 : "=r"(r0), "=r"(r1), "=r"(r2), "=r"(r3) : "r"(addr));
}
__device__ __forceinline__ void mma_f16(float* d, const uint32_t* a, const uint32_t* b) {
    asm volatile("mma.sync.aligned.m16n8k16.row.col.f32.f16.f16.f32 "
                 "{%0,%1,%2,%3}, {%4,%5,%6,%7}, {%8,%9}, {%0,%1,%2,%3};"
                 : "+f"(d[0]), "+f"(d[1]), "+f"(d[2]), "+f"(d[3])
                 : "r"(a[0]), "r"(a[1]), "r"(a[2]), "r"(a[3]), "r"(b[0]), "r"(b[1]));
}
// byte offset of 16B chunk (row, chunk) in 256B-row swizzled layout
__device__ __forceinline__ uint32_t sw(int row, int chunk) {
    return (uint32_t)(row * 256 + ((chunk ^ (row & 7)) << 4));
}
// 8 fp32 -> 8 fp16 packed (one 16B chunk)
__device__ __forceinline__ uint4 cvt8_f16(float4 a, float4 b) {
    __half2 h0 = __floats2half2_rn(a.x, a.y);
    __half2 h1 = __floats2half2_rn(a.z, a.w);
    __half2 h2 = __floats2half2_rn(b.x, b.y);
    __half2 h3 = __floats2half2_rn(b.z, b.w);
    return make_uint4(*(uint32_t*)&h0, *(uint32_t*)&h1,
                      *(uint32_t*)&h2, *(uint32_t*)&h3);
}

// ===========================================================================
// Kernel 1: one-tile-per-CTA fp16 GEMM on mma.sync, fused fp32->fp16 convert.
// Tile M=128, N=128, K=128. 320 CTAs at 2/SM (128-reg cap, ~110 live, no
// spill) -> 1.08 waves. Single copy->mma->store pass per CTA.
// Smem: A 32 KB + B 32 KB fp16, 256B rows, chunk XOR-swizzle (row&7).
// ===========================================================================
#define A_OFF 0
#define B_OFF 32768
#define SMEM_DYN (65536 + 1024)

__global__ __launch_bounds__(256, 2) void build_table_kernel(
    const float* __restrict__ E,
    const float* __restrict__ P,
    const float* __restrict__ scale_p)
{
    extern __shared__ char smem_raw[];
    const uint32_t sb0   = smem_u32(smem_raw);
    const uint32_t pad   = ((sb0 + 1023) & ~1023u) - sb0;
    char* smp            = smem_raw + pad;
    const uint32_t sbase = sb0 + pad;

    const int tid = threadIdx.x;
    const int m0  = blockIdx.x * 128;
    const int n0  = blockIdx.y * 128;

    // ---- copy+convert: A and B each 2048 chunks (128 rows x 16), 8/thread
    #pragma unroll
    for (int i = 0; i < 8; i++) {
        const int idx = i * 256 + tid;
        const int row = idx >> 4, chunk = idx & 15;
        const float4* g = (const float4*)(E + (size_t)(m0 + row) * PROJ_DIM + chunk * 8);
        *(uint4*)(smp + A_OFF + sw(row, chunk)) = cvt8_f16(__ldg(g), __ldg(g + 1));
    }
    #pragma unroll
    for (int i = 0; i < 8; i++) {
        const int idx = i * 256 + tid;
        const int row = idx >> 4, chunk = idx & 15;
        const float4* g = (const float4*)(P + (size_t)(n0 + row) * PROJ_DIM + chunk * 8);
        *(uint4*)(smp + B_OFF + sw(row, chunk)) = cvt8_f16(__ldg(g), __ldg(g + 1));
    }
    __syncthreads();

    // ---- mma: warp w -> rows wm*32..+31, cols wn*64..+63
    const int w    = tid >> 5;
    const int lane = tid & 31;
    const int wm   = w & 3;
    const int wn   = w >> 2;

    float acc[2][8][4];
    #pragma unroll
    for (int mf = 0; mf < 2; mf++)
        #pragma unroll
        for (int nf = 0; nf < 8; nf++)
            #pragma unroll
            for (int q = 0; q < 4; q++) acc[mf][nf][q] = 0.0f;

    int rowA[2], rowB[4];
    #pragma unroll
    for (int mf = 0; mf < 2; mf++)
        rowA[mf] = wm * 32 + mf * 16 + (lane & 7) + (lane & 8);
    #pragma unroll
    for (int bp = 0; bp < 4; bp++)
        rowB[bp] = wn * 64 + bp * 16 + (lane & 7) + ((lane & 16) >> 1);
    const int ckA = lane >> 4;
    const int ckB = (lane >> 3) & 1;

    #pragma unroll
    for (int kk = 0; kk < 8; kk++) {
        uint32_t ah[2][4];
        #pragma unroll
        for (int mf = 0; mf < 2; mf++) {
            const uint32_t off = sw(rowA[mf], 2 * kk + ckA);
            ldsm_x4(ah[mf][0], ah[mf][1], ah[mf][2], ah[mf][3], sbase + A_OFF + off);
        }
        uint32_t bh[8][2];
        #pragma unroll
        for (int bp = 0; bp < 4; bp++) {
            const uint32_t off = sw(rowB[bp], 2 * kk + ckB);
            ldsm_x4(bh[2 * bp][0], bh[2 * bp][1], bh[2 * bp + 1][0], bh[2 * bp + 1][1],
                    sbase + B_OFF + off);
        }
        #pragma unroll
        for (int mf = 0; mf < 2; mf++)
            #pragma unroll
            for (int nf = 0; nf < 8; nf++)
                mma_f16(acc[mf][nf], ah[mf], bh[nf]);
    }

    // ---- epilogue: scale + streaming store
    const float s = __ldg(scale_p);
    #pragma unroll
    for (int mf = 0; mf < 2; mf++) {
        const int r0 = m0 + wm * 32 + mf * 16 + (lane >> 2);
        #pragma unroll
        for (int nf = 0; nf < 8; nf++) {
            const int c = n0 + wn * 64 + nf * 8 + (lane & 3) * 2;
            float2 v0 = make_float2(acc[mf][nf][0] * s, acc[mf][nf][1] * s);
            float2 v1 = make_float2(acc[mf][nf][2] * s, acc[mf][nf][3] * s);
            __stcs((float2*)&g_fused[(size_t)r0 * MODEL_DIM + c], v0);
            __stcs((float2*)&g_fused[(size_t)(r0 + 8) * MODEL_DIM + c], v1);
        }
    }
}

// ===========================================================================
// Kernel 2: hash + gather + stream out (LTS-bound near cap; unchanged).
// ===========================================================================
__device__ __forceinline__ int hash_at(const int* __restrict__ tok, int t) {
    const int s = t & (SEQ - 1);
    if (s == 0) return HASH_SIZE - 1;
    const int t1 = __ldg(tok + t);
    const int t0 = __ldg(tok + t - 1);
    // products < 2^31: no wrap; matches jnp.mod exactly
    return ((36313 * t1) ^ (27191 * t0)) % (HASH_SIZE - 1);
}

__global__ __launch_bounds__(256) void gather_kernel(
    const int* __restrict__ tok,
    float* __restrict__ out)
{
    const int warp = (blockIdx.x * 256 + threadIdx.x) >> 5;
    const int lane = threadIdx.x & 31;
    const int tA = warp * 2, tB = warp * 2 + 1;

    const int hA = hash_at(tok, tA);
    const int hB = hash_at(tok, tB);

    const float4* sA = (const float4*)(g_fused + (size_t)hA * MODEL_DIM);
    const float4* sB = (const float4*)(g_fused + (size_t)hB * MODEL_DIM);
    float4* dA = (float4*)(out + (size_t)tA * MODEL_DIM);
    float4* dB = (float4*)(out + (size_t)tB * MODEL_DIM);

    float4 a0 = __ldg(sA + lane);
    float4 a1 = __ldg(sA + lane + 32);
    float4 a2 = __ldg(sA + lane + 64);
    float4 a3 = __ldg(sA + lane + 96);
    float4 b0 = __ldg(sB + lane);
    float4 b1 = __ldg(sB + lane + 32);
    float4 b2 = __ldg(sB + lane + 64);
    float4 b3 = __ldg(sB + lane + 96);

    __stcs(dA + lane,      a0);
    __stcs(dA + lane + 32, a1);
    __stcs(dA + lane + 64, a2);
    __stcs(dA + lane + 96, a3);
    __stcs(dB + lane,      b0);
    __stcs(dB + lane + 32, b1);
    __stcs(dB + lane + 64, b2);
    __stcs(dB + lane + 96, b3);
}

// ===========================================================================
// Inputs (metadata order): token_ids(i32), embed_weight(f32), proj_weight(f32), scale(f32[1])
// ===========================================================================
extern "C" void kernel_launch(void* const* d_in, const int* in_sizes, int n_in,
                              void* d_out, int out_size)
{
    const int*   tok   = (const int*)d_in[0];
    const float* E     = (const float*)d_in[1];
    const float* P     = (const float*)d_in[2];
    const float* scale = (const float*)d_in[3];
    float*       out   = (float*)d_out;

    cudaFuncSetAttribute(build_table_kernel,
                         cudaFuncAttributeMaxDynamicSharedMemorySize, SMEM_DYN);

    dim3 gemm_grid(HASH_SIZE / 128, MODEL_DIM / 128);   // (80, 4) = 320 CTAs
    build_table_kernel<<<gemm_grid, 256, SMEM_DYN>>>(E, P, scale);

    gather_kernel<<<(NBATCH * SEQ) / 16, 256>>>(tok, out);
}